// round 17
// baseline (speedup 1.0000x reference)
#include <cuda_runtime.h>
#include <cuda_fp16.h>
#include <cstdint>

// ============================================================================
// Problem constants
// ============================================================================
#define M_DIM 4096
#define K_DIM 4096
#define S_DIM 2048
#define N_DIM 16384            // B*S = 8*2048

#define BM 256
#define BN 128
#define BK 64                  // fp16: 64 k-elems = 128B per row chunk
#define K_ITERS (K_DIM / BK)   // 64
#define STAGES 4
#define K_OUTER (K_ITERS / STAGES)   // 16

#define THREADS 256            // 8 warps (4m x 2n, warp tile 64x64); warp0-lane0 produces

// Stage: A 256x64 fp16 (32KB) + B 128x64 fp16 (16KB), packed 128B/row
#define A_STAGE_BYTES 32768
#define B_STAGE_BYTES 16384
#define STAGE_BYTES   (A_STAGE_BYTES + B_STAGE_BYTES)   // 49152
#define SMEM_STAGE0   1024
#define SMEM_BYTES    (SMEM_STAGE0 + STAGES * STAGE_BYTES)  // 197632

// mbarriers: full[s] at s*16, empty[s] at s*16+8
#define MB_FULL(s)  ((s) * 16)
#define MB_EMPTY(s) ((s) * 16 + 8)

// conv_x blocks per kb slab: N_DIM*8 granules / 256 threads = 512
#define CONV_BLOCKS_PER_KB 512

// ============================================================================
// Scratch (device globals)
//
// g_Wh/g_Xh: fp16 blocked [kb][row][64]  (kb = k/64, chunk = 128B row).
// Within a 64-half chunk, logical k index j (0..63) stored at half index:
//   l = j>>3 (16B granule 0..7), stored granule = l ^ (row & 7)
//   half_idx = (l ^ (row&7))*8 + (j&7)
// => ldmatrix tiles (8 consecutive rows x one logical granule) hit 8 distinct
//    stored granules -> conflict-free.
// g_Wh is ALSO the scatter-add target (fp16 atomics, blocked address).
// g_done[kb]: conv_x completion counters (block count) gating GEMM B loads.
// ============================================================================
__device__ __align__(128) __half g_Wh[(size_t)M_DIM * K_DIM];   // 32 MB
__device__ __align__(128) __half g_Xh[(size_t)N_DIM * K_DIM];   // 128 MB
__device__ int g_done[K_ITERS];

// ============================================================================
// Helpers
// ============================================================================
__device__ __forceinline__ uint32_t smem_u32(const void* p) {
    uint32_t a;
    asm("{ .reg .u64 t; cvta.to.shared.u64 t, %1; cvt.u32.u64 %0, t; }"
        : "=r"(a) : "l"(p));
    return a;
}

// ldmatrix x4 with compile-time immediate offset.
template <int IMM>
__device__ __forceinline__ void ldsm_x4(uint32_t* r, uint32_t addr) {
    asm volatile("ldmatrix.sync.aligned.m8n8.x4.shared.b16 {%0,%1,%2,%3}, [%4+%5];"
                 : "=r"(r[0]), "=r"(r[1]), "=r"(r[2]), "=r"(r[3])
                 : "r"(addr), "n"(IMM));
}

// m16n8k16 fp16 MMA, fp32 accumulate.
__device__ __forceinline__ void mma_f16(float* c,
                                        uint32_t a0, uint32_t a1,
                                        uint32_t a2, uint32_t a3,
                                        uint32_t b0, uint32_t b1) {
    asm volatile(
        "mma.sync.aligned.m16n8k16.row.col.f32.f16.f16.f32 "
        "{%0,%1,%2,%3}, {%4,%5,%6,%7}, {%8,%9}, {%0,%1,%2,%3};"
        : "+f"(c[0]), "+f"(c[1]), "+f"(c[2]), "+f"(c[3])
        : "r"(a0), "r"(a1), "r"(a2), "r"(a3), "r"(b0), "r"(b1));
}

// Spin until conv_x finished kb (producer thread only).
__device__ __forceinline__ void wait_kb(int kb) {
    const volatile int* p = g_done + kb;
    while (*p < CONV_BLOCKS_PER_KB) {
        asm volatile("nanosleep.u32 128;");
    }
}

#define MBARRIER_INIT(mbar, count) \
    asm volatile("mbarrier.init.shared.b64 [%0], %1;" \
                 :: "r"((uint32_t)(mbar)), "r"((uint32_t)(count)) : "memory")

#define MBARRIER_ARRIVE(mbar) \
    asm volatile("mbarrier.arrive.shared.b64 _, [%0];" \
                 :: "r"((uint32_t)(mbar)) : "memory")

#define MBARRIER_EXPECT_TX(mbar, tx_bytes) \
    asm volatile("mbarrier.arrive.expect_tx.shared.b64 _, [%0], %1;" \
                 :: "r"((uint32_t)(mbar)), "r"((uint32_t)(tx_bytes)) : "memory")

#define MBARRIER_WAIT_PARITY(mbar, parity) do {                                   \
    uint32_t _mbar = (uint32_t)(mbar);                                            \
    uint32_t _par = (uint32_t)(parity);                                           \
    uint32_t _done;                                                               \
    asm volatile(                                                                 \
        "{\n\t.reg .pred p;\n\t"                                                  \
        "mbarrier.try_wait.parity.acquire.cta.shared::cta.b64 p, [%1], %2;\n\t"   \
        "selp.b32 %0, 1, 0, p;\n\t}"                                              \
        : "=r"(_done) : "r"(_mbar), "r"(_par) : "memory");                        \
    if (!_done) {                                                                 \
        asm volatile(                                                             \
            "{\n\t.reg .pred P1;\n\t"                                             \
            "WAIT_LOOP_%=:\n\t"                                                   \
            "mbarrier.try_wait.parity.acquire.cta.shared::cta.b64 P1, [%0], %1, 0x989680;\n\t" \
            "@P1 bra.uni WAIT_DONE_%=;\n\t"                                       \
            "bra.uni WAIT_LOOP_%=;\n\t"                                           \
            "WAIT_DONE_%=:\n\t}"                                                  \
            :: "r"(_mbar), "r"(_par) : "memory");                                 \
    }                                                                             \
} while (0)

#define MBARRIER_WAIT_PARITY_RELAXED(mbar, parity) do {                           \
    uint32_t _mbar = (uint32_t)(mbar);                                            \
    uint32_t _par = (uint32_t)(parity);                                           \
    uint32_t _done;                                                               \
    asm volatile(                                                                 \
        "{\n\t.reg .pred p;\n\t"                                                  \
        "mbarrier.try_wait.parity.relaxed.cta.shared::cta.b64 p, [%1], %2, 0x989680;\n\t" \
        "selp.b32 %0, 1, 0, p;\n\t}"                                              \
        : "=r"(_done) : "r"(_mbar), "r"(_par) : "memory");                        \
    if (!_done) {                                                                 \
        asm volatile(                                                             \
            "{\n\t.reg .pred P1;\n\t"                                             \
            "WAIT_LOOP_%=:\n\t"                                                   \
            "mbarrier.try_wait.parity.relaxed.cta.shared::cta.b64 P1, [%0], %1, 0x989680;\n\t" \
            "@P1 bra.uni WAIT_DONE_%=;\n\t"                                       \
            "bra.uni WAIT_LOOP_%=;\n\t"                                           \
            "WAIT_DONE_%=:\n\t}"                                                  \
            :: "r"(_mbar), "r"(_par) : "memory");                                 \
    }                                                                             \
} while (0)

#define BULK_G2S(dst_smem, src_gmem, nbytes, mbar)                                \
    asm volatile(                                                                 \
        "cp.async.bulk.shared::cta.global.mbarrier::complete_tx::bytes "          \
        "[%0], [%1], %2, [%3];"                                                   \
        :: "r"((uint32_t)(dst_smem)), "l"(src_gmem),                              \
           "r"((uint32_t)(nbytes)), "r"((uint32_t)(mbar)) : "memory")

// ============================================================================
// Pre-pass kernels
// ============================================================================

// COO scatter-add DIRECTLY into the fp16 blocked+XOR layout.
__global__ void scatter_kernel(const float* __restrict__ vals,
                               const int* __restrict__ rows,
                               const int* __restrict__ cols, int nnz) {
    int i = blockIdx.x * blockDim.x + threadIdx.x;
    if (i < nnz) {
        int r  = rows[i], c = cols[i];
        int kb = c >> 6;                 // BK = 64
        int j  = c & 63;
        int l  = j >> 3;
        int g  = l ^ (r & 7);
        size_t off = (size_t)kb * (M_DIM * BK) + (size_t)r * BK + g * 8 + (j & 7);
        atomicAdd(&g_Wh[off], __float2half(vals[i]));
    }
}

// Convert 8 fp32 -> one 16B fp16 granule (register-only, no local memory).
__device__ __forceinline__ uint4 cvt8(const float4* s) {
    float4 f0 = s[0];
    float4 f1 = s[1];
    __half2 h0 = __float22half2_rn(make_float2(f0.x, f0.y));
    __half2 h1 = __float22half2_rn(make_float2(f0.z, f0.w));
    __half2 h2 = __float22half2_rn(make_float2(f1.x, f1.y));
    __half2 h3 = __float22half2_rn(make_float2(f1.z, f1.w));
    uint4 o;
    o.x = *reinterpret_cast<uint32_t*>(&h0);
    o.y = *reinterpret_cast<uint32_t*>(&h1);
    o.z = *reinterpret_cast<uint32_t*>(&h2);
    o.w = *reinterpret_cast<uint32_t*>(&h3);
    return o;
}

// x (fp32 natural) -> g_Xh (fp16 blocked + granule-XOR).
// kb-major block order; each block signals g_done[kb] when its slab part lands.
__global__ void conv_x_kernel(const float* __restrict__ x) {
    int kb    = blockIdx.x >> 9;                 // 512 blocks per kb
    int inner = blockIdx.x & 511;
    int gid   = inner * 256 + threadIdx.x;       // 0..131071 within slab
    int g     = gid & 7;
    int n     = gid >> 3;
    int l     = g ^ (n & 7);
    const float4* src = reinterpret_cast<const float4*>(
        x + (size_t)n * K_DIM + kb * BK + l * 8);
    uint4* dst = reinterpret_cast<uint4*>(
        g_Xh + (size_t)kb * (N_DIM * BK) + (size_t)n * BK + g * 8);
    *dst = cvt8(src);

    __syncthreads();
    if (threadIdx.x == 0) {
        __threadfence();
        atomicAdd(&g_done[kb], 1);
    }
}

// ============================================================================
// Mainloop: warp tile 64(m) x 64(n), m16n8k16, 4 ksteps (K=16) per k-iter.
// Per kstep: 4 A ldmatrix.x4 + 4 B ldmatrix.x4, 32 MMAs. Literal-imm offsets.
// ============================================================================
#define KSTEP(S, KS) do {                                                       \
    uint32_t a[4][4], bb[16];                                                   \
    ldsm_x4<(S)*STAGE_BYTES +    0>(a[0], aAddr[KS]);                           \
    ldsm_x4<(S)*STAGE_BYTES + 2048>(a[1], aAddr[KS]);                           \
    ldsm_x4<(S)*STAGE_BYTES + 4096>(a[2], aAddr[KS]);                           \
    ldsm_x4<(S)*STAGE_BYTES + 6144>(a[3], aAddr[KS]);                           \
    ldsm_x4<(S)*STAGE_BYTES +    0>(bb,      bAddr[KS]);                        \
    ldsm_x4<(S)*STAGE_BYTES + 2048>(bb +  4, bAddr[KS]);                        \
    ldsm_x4<(S)*STAGE_BYTES + 4096>(bb +  8, bAddr[KS]);                        \
    ldsm_x4<(S)*STAGE_BYTES + 6144>(bb + 12, bAddr[KS]);                        \
    _Pragma("unroll")                                                           \
    for (int ni = 0; ni < 8; ni++) {                                            \
        _Pragma("unroll")                                                       \
        for (int mi = 0; mi < 4; mi++) {                                        \
            mma_f16(acc[mi][ni], a[mi][0], a[mi][1], a[mi][2], a[mi][3],        \
                    bb[ni * 2], bb[ni * 2 + 1]);                                \
        }                                                                       \
    }                                                                           \
} while (0)

#define CONSUME_STAGE(S) do {                                                   \
    MBARRIER_WAIT_PARITY(sbase + MB_FULL(S), ph);                               \
    KSTEP(S, 0); KSTEP(S, 1); KSTEP(S, 2); KSTEP(S, 3);                         \
    __syncwarp();                                                               \
    if (lane == 0) MBARRIER_ARRIVE(sbase + MB_EMPTY(S));                        \
    if (tid == 0 && ko < K_OUTER - 1) {                                         \
        /* refill this slot with k-iter (4*ko + S + 4) */                       \
        MBARRIER_WAIT_PARITY_RELAXED(sbase + MB_EMPTY(S), ph);                  \
        const int knext = 4 * ko + (S) + 4;                                     \
        wait_kb(knext);                                                         \
        uint32_t full = sbase + MB_FULL(S);                                     \
        uint32_t dst  = sbase + SMEM_STAGE0 + (S) * STAGE_BYTES;                \
        MBARRIER_EXPECT_TX(full, STAGE_BYTES);                                  \
        BULK_G2S(dst, Asrc0 + (size_t)knext * (M_DIM * BK),                     \
                 A_STAGE_BYTES, full);                                          \
        BULK_G2S(dst + A_STAGE_BYTES, Bsrc0 + (size_t)knext * (N_DIM * BK),     \
                 B_STAGE_BYTES, full);                                          \
    }                                                                           \
} while (0)

// ============================================================================
// fp16 GEMM: out[b,m,s] = sum_k W[m,k]*X[n,k] + bias[s],  n = b*2048 + s
// CTA tile 256x128; 8 warps (2 per SMSP), warp0-lane0 doubles as producer.
// B loads gated on conv_x per-kb completion flags (overlapped conversion).
// ============================================================================
__global__ void __launch_bounds__(THREADS, 1) gemm_kernel(
    const float* __restrict__ bias, float* __restrict__ out)
{
    extern __shared__ uint32_t smem[];
    const uint32_t sbase = smem_u32(smem);

    const int tid  = threadIdx.x;
    const int wid  = tid >> 5;
    const int lane = tid & 31;

    // CTA tile mapping: bid = mt + 16*nt (wave covers all 16 m-tiles -> A reuse)
    const int mt = blockIdx.x & 15;
    const int nt = blockIdx.x >> 4;
    const int m0 = mt * BM;
    const int n0 = nt * BN;

    const __half* Asrc0 = g_Wh + (size_t)m0 * BK;
    const __half* Bsrc0 = g_Xh + (size_t)n0 * BK;

    if (tid == 0) {
        #pragma unroll
        for (int s = 0; s < STAGES; s++) {
            MBARRIER_INIT(sbase + MB_FULL(s), 1);
            MBARRIER_INIT(sbase + MB_EMPTY(s), 8);
        }
    }
    __syncthreads();

    // Prologue: fill all 4 stages (k = 0..3), gated on conv_x progress
    if (tid == 0) {
        #pragma unroll
        for (int s = 0; s < STAGES; s++) {
            wait_kb(s);
            uint32_t full = sbase + MB_FULL(s);
            uint32_t dst  = sbase + SMEM_STAGE0 + s * STAGE_BYTES;
            MBARRIER_EXPECT_TX(full, STAGE_BYTES);
            BULK_G2S(dst, Asrc0 + (size_t)s * (M_DIM * BK), A_STAGE_BYTES, full);
            BULK_G2S(dst + A_STAGE_BYTES, Bsrc0 + (size_t)s * (N_DIM * BK),
                     B_STAGE_BYTES, full);
        }
    }

    // ------------------------- Fragment addressing -------------------------
    const int wm = wid & 3;         // warp m index 0..3 (64 rows each)
    const int wn = wid >> 2;        // warp n index 0..1 (64 rows each)
    const int l7 = lane & 7;        // XOR key == (stage row & 7) for all tiles

    // A ldmatrix lane row: lanes 0-15 -> rows 0-15 (k-lo), 16-31 -> rows (k-hi)
    const int rA = lane & 15;
    const int hA = lane >> 4;
    // B ldmatrix lane row: 0-7/8-15 -> rows of ni (k-lo/k-hi); 16-31 -> ni+1
    const int rB = (lane & 7) + ((lane & 16) >> 1);
    const int hB = (lane >> 3) & 1;

    uint32_t aAddr[4], bAddr[4];
    #pragma unroll
    for (int ks = 0; ks < 4; ks++) {
        aAddr[ks] = sbase + SMEM_STAGE0
                  + (uint32_t)((wm * 64 + rA) * 128)
                  + (uint32_t)(((2 * ks + hA) ^ l7) << 4);
        bAddr[ks] = sbase + SMEM_STAGE0 + A_STAGE_BYTES
                  + (uint32_t)((wn * 64 + rB) * 128)
                  + (uint32_t)(((2 * ks + hB) ^ l7) << 4);
    }

    float acc[4][8][4];
#pragma unroll
    for (int i = 0; i < 4; i++)
#pragma unroll
        for (int j = 0; j < 8; j++)
#pragma unroll
            for (int r = 0; r < 4; r++) acc[i][j][r] = 0.0f;

    for (int ko = 0; ko < K_OUTER; ko++) {
        const int ph = ko & 1;
        CONSUME_STAGE(0);
        CONSUME_STAGE(1);
        CONSUME_STAGE(2);
        CONSUME_STAGE(3);
    }

    // ------------------------------------------------------------------------
    // Epilogue: out[b, m, s] = acc + bias[s]; CTA tile lies in one batch
    // m16n8k16 accum: c0,c1 -> row g cols 2t,2t+1; c2,c3 -> row g+8
    // ------------------------------------------------------------------------
    const int g = lane >> 2;
    const int t = lane & 3;
    const int b   = n0 >> 11;        // n0 / 2048
    const int s0c = n0 & 2047;
    float* obase = out + (size_t)b * M_DIM * S_DIM;

#pragma unroll
    for (int mi = 0; mi < 4; mi++) {
#pragma unroll
        for (int ni = 0; ni < 8; ni++) {
            int sl = s0c + wn * 64 + ni * 8 + 2 * t;
            float2 bv = *reinterpret_cast<const float2*>(bias + sl);
            int m = m0 + wm * 64 + mi * 16 + g;

            float2 v0;
            v0.x = acc[mi][ni][0] + bv.x;
            v0.y = acc[mi][ni][1] + bv.y;
            *reinterpret_cast<float2*>(obase + (size_t)m * S_DIM + sl) = v0;

            float2 v1;
            v1.x = acc[mi][ni][2] + bv.x;
            v1.y = acc[mi][ni][3] + bv.y;
            *reinterpret_cast<float2*>(obase + (size_t)(m + 8) * S_DIM + sl) = v1;
        }
    }
}

// ============================================================================
// Host launch — conv_x runs CONCURRENTLY with the GEMM on a side stream;
// the GEMM's B loads are gated per-kb by g_done flags. The join event is
// waited on AFTER the gemm launch (graph completeness without serialization).
// ============================================================================
extern "C" void kernel_launch(void* const* d_in, const int* in_sizes, int n_in,
                              void* d_out, int out_size) {
    const float* x      = (const float*)d_in[0];
    const float* values = (const float*)d_in[1];
    const float* bias   = (const float*)d_in[2];
    const int* row_ids  = (const int*)d_in[3];
    const int* col_idx  = (const int*)d_in[4];
    int nnz = in_sizes[1];
    float* out = (float*)d_out;

    // One-time resources (created on the uncaptured correctness call).
    static cudaStream_t s2 = nullptr;
    static cudaEvent_t ev_fork = nullptr, ev_join = nullptr;
    static bool attr_set = false;
    if (!attr_set) {
        cudaStreamCreateWithFlags(&s2, cudaStreamNonBlocking);
        cudaEventCreateWithFlags(&ev_fork, cudaEventDisableTiming);
        cudaEventCreateWithFlags(&ev_join, cudaEventDisableTiming);
        cudaFuncSetAttribute(gemm_kernel,
                             cudaFuncAttributeMaxDynamicSharedMemorySize,
                             SMEM_BYTES);
        attr_set = true;
    }

    void* whptr = nullptr;
    void* doneptr = nullptr;
    cudaGetSymbolAddress(&whptr, g_Wh);
    cudaGetSymbolAddress(&doneptr, g_done);

    // ---- reset conv-x progress flags (before the fork) ----
    cudaMemsetAsync(doneptr, 0, K_ITERS * sizeof(int));

    // ---- branch: conv_x depends only on input x; runs under the GEMM ----
    cudaEventRecord(ev_fork, 0);
    cudaStreamWaitEvent(s2, ev_fork, 0);
    conv_x_kernel<<<K_ITERS * CONV_BLOCKS_PER_KB, 256, 0, s2>>>(x);
    cudaEventRecord(ev_join, s2);

    // ---- main chain: zero fp16 W, scatter-add in fp16 blocked layout ----
    cudaMemsetAsync(whptr, 0, (size_t)M_DIM * K_DIM * sizeof(__half));
    scatter_kernel<<<(nnz + 255) / 256, 256>>>(values, row_ids, col_idx, nnz);

    // ---- GEMM launches immediately; its producer polls g_done per kb ----
    gemm_kernel<<<(M_DIM / BM) * (N_DIM / BN), THREADS, SMEM_BYTES>>>(bias, out);

    // ---- join the side stream after the gemm (graph completeness) ----
    cudaStreamWaitEvent(0, ev_join, 0);
}